// round 2
// baseline (speedup 1.0000x reference)
#include <cuda_runtime.h>
#include <math.h>

// ---------------- problem constants ----------------
// x:(8,128,64,64) w_dw:(64,1,5,5) ln_w:(64) w_off:(3,64) wq/wk/wv/wo:(128,128) rpe:(4,127,127)
#define B_   8
#define C_   128
#define HW_  4096
#define NKV_ 256
#define RPE_N 16129     // 127*127

// ---------------- device scratch (no runtime alloc) ----------------
__device__ float g_q  [B_ * C_ * HW_];   // q projection
__device__ float g_ao [B_ * C_ * HW_];   // attention output
__device__ float g_off[16 * 64 * NKV_]; // depthwise conv out (B*G, 64, 256)
__device__ float g_pos[16 * NKV_ * 2];  // (B*G, 256, {y,x})
__device__ float g_dm [16 * NKV_];      // modulation
__device__ float g_xs [B_ * C_ * NKV_]; // sampled*dm, layout [b][ic][n]
__device__ float g_k  [B_ * C_ * NKV_];
__device__ float g_v  [B_ * C_ * NKV_];

// ---------------- generic 128xK tile GEMM: Y[b][oc][p] = sum_k A[oc][k] X[b][k][p] ----------------
__device__ __forceinline__ void gemm_tile(
    const float* __restrict__ A, const float* __restrict__ X,
    float* __restrict__ Y, int ld)
{
    extern __shared__ float sm[];
    float* a_sm = sm;           // [128][128]
    float* b_sm = sm + 16384;   // [128][128] (k, p)
    int tid = threadIdx.x;

    for (int i = tid; i < 4096; i += 256)
        ((float4*)a_sm)[i] = ((const float4*)A)[i];
    for (int i = tid; i < 4096; i += 256) {
        int k = i >> 5, p4 = (i & 31) * 4;
        *(float4*)(b_sm + k * 128 + p4) = *(const float4*)(X + (size_t)k * ld + p4);
    }
    __syncthreads();

    int tr = tid >> 4, tc = tid & 15;
    int oc0 = tr * 8, p0 = tc * 8;
    float acc[8][8];
#pragma unroll
    for (int i = 0; i < 8; i++)
#pragma unroll
        for (int j = 0; j < 8; j++) acc[i][j] = 0.f;

#pragma unroll 2
    for (int k = 0; k < 128; k++) {
        float av[8];
#pragma unroll
        for (int i = 0; i < 8; i++) av[i] = a_sm[(oc0 + i) * 128 + k];
        float4 b0 = *(float4*)(b_sm + k * 128 + p0);
        float4 b1 = *(float4*)(b_sm + k * 128 + p0 + 4);
#pragma unroll
        for (int i = 0; i < 8; i++) {
            acc[i][0] += av[i] * b0.x; acc[i][1] += av[i] * b0.y;
            acc[i][2] += av[i] * b0.z; acc[i][3] += av[i] * b0.w;
            acc[i][4] += av[i] * b1.x; acc[i][5] += av[i] * b1.y;
            acc[i][6] += av[i] * b1.z; acc[i][7] += av[i] * b1.w;
        }
    }
#pragma unroll
    for (int i = 0; i < 8; i++) {
        float* yr = Y + (size_t)(oc0 + i) * ld + p0;
        *(float4*)yr       = make_float4(acc[i][0], acc[i][1], acc[i][2], acc[i][3]);
        *(float4*)(yr + 4) = make_float4(acc[i][4], acc[i][5], acc[i][6], acc[i][7]);
    }
}

__global__ void __launch_bounds__(256) gemm128_kernel(
    const float* __restrict__ A, const float* __restrict__ X,
    float* __restrict__ Y, int ld, int ntiles)
{
    int b  = blockIdx.x / ntiles;
    int pb = (blockIdx.x % ntiles) * 128;
    gemm_tile(A, X + (size_t)b * 128 * ld + pb, Y + (size_t)b * 128 * ld + pb, ld);
}

__global__ void __launch_bounds__(256) gemm_kv_kernel(
    const float* __restrict__ wk, const float* __restrict__ wv)
{
    int sel = blockIdx.x >> 4;           // 0: k, 1: v
    int r   = blockIdx.x & 15;
    int b   = r >> 1;
    int pb  = (r & 1) * 128;
    const float* A = sel ? wv : wk;
    float* Y = sel ? g_v : g_k;
    gemm_tile(A, g_xs + (size_t)b * 128 * NKV_ + pb, Y + (size_t)b * 128 * NKV_ + pb, NKV_);
}

// ---------------- depthwise 5x5 stride-4 pad-2 on q groups ----------------
__global__ void __launch_bounds__(256) dwconv_kernel(const float* __restrict__ w_dw)
{
    __shared__ float plane[4096];
    __shared__ float ws[25];
    int bid = blockIdx.x;                // 16*64
    int bg = bid >> 6, c = bid & 63;
    int b = bg >> 1, g = bg & 1;
    int tid = threadIdx.x;

    const float* src = g_q + ((size_t)(b * 128 + g * 64 + c)) * HW_;
    for (int i = tid; i < 1024; i += 256)
        ((float4*)plane)[i] = ((const float4*)src)[i];
    if (tid < 25) ws[tid] = w_dw[c * 25 + tid];
    __syncthreads();

    int i = tid >> 4, j = tid & 15;
    int y0 = 4 * i - 2, x0 = 4 * j - 2;
    float acc = 0.f;
#pragma unroll
    for (int u = 0; u < 5; u++) {
        int yy = y0 + u;
        if ((unsigned)yy < 64u) {
#pragma unroll
            for (int v = 0; v < 5; v++) {
                int xx = x0 + v;
                if ((unsigned)xx < 64u) acc += plane[yy * 64 + xx] * ws[u * 5 + v];
            }
        }
    }
    g_off[((size_t)(bg * 64 + c)) * NKV_ + tid] = acc;
}

// ---------------- LN(var-only) + exact GELU + 1x1 -> offsets/modulation ----------------
__global__ void __launch_bounds__(256) offhead_kernel(
    const float* __restrict__ ln_w, const float* __restrict__ w_off)
{
    int bg = blockIdx.x;
    int sp = threadIdx.x;
    const float* base = g_off + (size_t)bg * 64 * NKV_ + sp;
    float v[64];
    float s = 0.f, s2 = 0.f;
#pragma unroll
    for (int c = 0; c < 64; c++) {
        float t = base[c * NKV_];
        v[c] = t; s += t; s2 += t * t;
    }
    float mean = s * (1.f / 64.f);
    float var  = s2 * (1.f / 64.f) - mean * mean;
    float rstd = rsqrtf(var + 1e-5f);

    float o0 = 0.f, o1 = 0.f, o2 = 0.f;
#pragma unroll
    for (int c = 0; c < 64; c++) {
        float t = v[c] * rstd * __ldg(&ln_w[c]);
        float ge = 0.5f * t * (1.f + erff(t * 0.70710678118654752f));
        o0 += __ldg(&w_off[c]) * ge;
        o1 += __ldg(&w_off[64 + c]) * ge;
        o2 += __ldg(&w_off[128 + c]) * ge;
    }
    int i = sp >> 4, j = sp & 15;
    float ry = (float)(2 * i + 1) * (1.f / 16.f) - 1.f;
    float rx = (float)(2 * j + 1) * (1.f / 16.f) - 1.f;
    g_pos[bg * 512 + sp * 2]     = tanhf(o0) * (1.f / 16.f) + ry;
    g_pos[bg * 512 + sp * 2 + 1] = tanhf(o1) * (1.f / 16.f) + rx;
    g_dm [bg * 256 + sp]         = 1.f / (1.f + expf(-o2));
}

// ---------------- bilinear grid-sample of x at deformed points, * dm ----------------
__global__ void __launch_bounds__(256) sample_kernel(const float* __restrict__ x)
{
    int blk = blockIdx.x;                // 64 blocks
    int bg = blk >> 2;
    int nblk = (blk & 3) * 64;
    int b = bg >> 1, g = bg & 1;
    int c = threadIdx.x & 63;
    int ni = threadIdx.x >> 6;
    const float* plane = x + ((size_t)(b * 128 + g * 64 + c)) * HW_;
    for (int nn = ni; nn < 64; nn += 4) {
        int n = nblk + nn;
        float py_ = g_pos[bg * 512 + n * 2];
        float px_ = g_pos[bg * 512 + n * 2 + 1];
        float dmv = g_dm[bg * 256 + n];
        float gx = (px_ + 1.f) * 31.5f;   // align_corners: (x+1)*0.5*(W-1)
        float gy = (py_ + 1.f) * 31.5f;
        float x0f = floorf(gx), y0f = floorf(gy);
        float wx = gx - x0f, wy = gy - y0f;
        int ix0 = (int)x0f, iy0 = (int)y0f;
        float v00 = 0.f, v01 = 0.f, v10 = 0.f, v11 = 0.f;
        bool xin0 = (unsigned)ix0 < 64u, xin1 = (unsigned)(ix0 + 1) < 64u;
        bool yin0 = (unsigned)iy0 < 64u, yin1 = (unsigned)(iy0 + 1) < 64u;
        if (yin0) { int r = iy0 * 64;      if (xin0) v00 = plane[r + ix0]; if (xin1) v01 = plane[r + ix0 + 1]; }
        if (yin1) { int r = (iy0 + 1) * 64; if (xin0) v10 = plane[r + ix0]; if (xin1) v11 = plane[r + ix0 + 1]; }
        float top = v00 + (v01 - v00) * wx;
        float bot = v10 + (v11 - v10) * wx;
        float val = top + (bot - top) * wy;
        g_xs[((size_t)(b * 128 + g * 64 + c)) * NKV_ + n] = val * dmv;
    }
}

// ---------------- fused attention: QK + rpe-bias + softmax + PV ----------------
// grid = 32 heads * 64 q-tiles; block = 512 thr; 1 block/SM (208 KB smem)
// smem layout (floats):
#define SM_RPE  0
#define SM_K    16132                 // [32][256]
#define SM_VS   (16132 + 8192)       // [256][33] transposed V
#define SM_Q    (SM_VS + 8448)       // [64][33]
#define SM_POS  (SM_Q + 2112)        // [256][2]
#define SM_P    (SM_POS + 512)       // [64][260]
#define ATTN_SMEM_FLOATS (SM_P + 64 * 260)

__global__ void __launch_bounds__(512) attn_kernel(const float* __restrict__ rpe)
{
    extern __shared__ float sm[];
    float* rpe_sm = sm + SM_RPE;
    float* k_sm   = sm + SM_K;
    float* vs_sm  = sm + SM_VS;
    float* q_sm   = sm + SM_Q;
    float* pos_sm = sm + SM_POS;
    float* p_sm   = sm + SM_P;

    int tid = threadIdx.x;
    int bh   = blockIdx.x >> 6;
    int tile = blockIdx.x & 63;
    int b = bh >> 2, h = bh & 3, g = h >> 1;
    int qbase = tile * 64;

    // ---- loads ----
    const float* rp = rpe + (size_t)h * RPE_N;
    for (int i = tid; i < RPE_N; i += 512) rpe_sm[i] = rp[i];

    const float* kb = g_k + ((size_t)(b * 128 + h * 32)) * NKV_;
    for (int i = tid; i < 2048; i += 512)
        ((float4*)k_sm)[i] = ((const float4*)kb)[i];

    const float* vb = g_v + ((size_t)(b * 128 + h * 32)) * NKV_;
    for (int i = tid; i < 8192; i += 512) {
        int c = i >> 8, n = i & 255;
        vs_sm[n * 33 + c] = vb[c * 256 + n];
    }
    const float* qb = g_q + ((size_t)(b * 128 + h * 32)) * HW_ + qbase;
    for (int i = tid; i < 2048; i += 512) {
        int c = i >> 6, qi = i & 63;
        q_sm[qi * 33 + c] = qb[(size_t)c * HW_ + qi];
    }
    pos_sm[tid] = g_pos[(size_t)(b * 2 + g) * 512 + tid];
    __syncthreads();

    // ---- phase A: QK + bias + softmax (warp = 4 queries, lane = 8 keys) ----
    int w = tid >> 5, l = tid & 31;
    int q0 = w * 4;
    int nb = l * 8;
    float py[8], px[8];
#pragma unroll
    for (int j = 0; j < 8; j++) {
        py[j] = pos_sm[(nb + j) * 2];
        px[j] = pos_sm[(nb + j) * 2 + 1];
    }
    float acc[4][8];
#pragma unroll
    for (int i = 0; i < 4; i++)
#pragma unroll
        for (int j = 0; j < 8; j++) acc[i][j] = 0.f;

    for (int c = 0; c < 32; c += 2) {
        float qv0[4], qv1[4];
#pragma unroll
        for (int i = 0; i < 4; i++) {
            qv0[i] = q_sm[(q0 + i) * 33 + c];
            qv1[i] = q_sm[(q0 + i) * 33 + c + 1];
        }
        float4 a0 = *(float4*)&k_sm[c * 256 + nb];
        float4 a1 = *(float4*)&k_sm[c * 256 + nb + 4];
        float4 c0 = *(float4*)&k_sm[(c + 1) * 256 + nb];
        float4 c1 = *(float4*)&k_sm[(c + 1) * 256 + nb + 4];
        float ka[8] = {a0.x, a0.y, a0.z, a0.w, a1.x, a1.y, a1.z, a1.w};
        float kc[8] = {c0.x, c0.y, c0.z, c0.w, c1.x, c1.y, c1.z, c1.w};
#pragma unroll
        for (int i = 0; i < 4; i++)
#pragma unroll
            for (int j = 0; j < 8; j++)
                acc[i][j] += qv0[i] * ka[j] + qv1[i] * kc[j];
    }

    const float scale = 0.17677669529663687f; // 32^-0.5
#pragma unroll
    for (int i = 0; i < 4; i++) {
        int m = qbase + q0 + i;
        float qy = (float)(2 * (m >> 6) + 1) * (1.f / 64.f) - 1.f;
        float qx = (float)(2 * (m & 63) + 1) * (1.f / 64.f) - 1.f;
        float sv[8];
#pragma unroll
        for (int j = 0; j < 8; j++) {
            float gx = ((qx - px[j]) * 0.5f + 1.f) * 63.f;  // (d+1)*0.5*(127-1)
            float gy = ((qy - py[j]) * 0.5f + 1.f) * 63.f;
            float x0f = floorf(gx), y0f = floorf(gy);
            float wx = gx - x0f, wy = gy - y0f;
            int ix0 = (int)x0f, iy0 = (int)y0f;
            float v00 = 0.f, v01 = 0.f, v10 = 0.f, v11 = 0.f;
            bool xin0 = (unsigned)ix0 < 127u, xin1 = (unsigned)(ix0 + 1) < 127u;
            bool yin0 = (unsigned)iy0 < 127u, yin1 = (unsigned)(iy0 + 1) < 127u;
            if (yin0) { int r = iy0 * 127;       if (xin0) v00 = rpe_sm[r + ix0]; if (xin1) v01 = rpe_sm[r + ix0 + 1]; }
            if (yin1) { int r = (iy0 + 1) * 127; if (xin0) v10 = rpe_sm[r + ix0]; if (xin1) v11 = rpe_sm[r + ix0 + 1]; }
            float top = v00 + (v01 - v00) * wx;
            float bot = v10 + (v11 - v10) * wx;
            sv[j] = acc[i][j] * scale + (top + (bot - top) * wy);
        }
        float mx = sv[0];
#pragma unroll
        for (int j = 1; j < 8; j++) mx = fmaxf(mx, sv[j]);
#pragma unroll
        for (int o = 16; o; o >>= 1) mx = fmaxf(mx, __shfl_xor_sync(0xffffffffu, mx, o));
        float sum = 0.f;
#pragma unroll
        for (int j = 0; j < 8; j++) { float e = __expf(sv[j] - mx); sv[j] = e; sum += e; }
#pragma unroll
        for (int o = 16; o; o >>= 1) sum += __shfl_xor_sync(0xffffffffu, sum, o);
        float inv = 1.f / sum;
#pragma unroll
        for (int j = 0; j < 8; j++) acc[i][j] = sv[j] * inv;
    }
#pragma unroll
    for (int i = 0; i < 4; i++) {
        *(float4*)&p_sm[(q0 + i) * 260 + nb]     = make_float4(acc[i][0], acc[i][1], acc[i][2], acc[i][3]);
        *(float4*)&p_sm[(q0 + i) * 260 + nb + 4] = make_float4(acc[i][4], acc[i][5], acc[i][6], acc[i][7]);
    }
    __syncthreads();

    // ---- phase B: PV (thread = 4 queries x 1 channel) ----
    int c2 = tid & 31, qg = tid >> 5;
    int q0b = qg * 4;
    float o0 = 0.f, o1 = 0.f, o2 = 0.f, o3 = 0.f;
#pragma unroll 4
    for (int n = 0; n < 256; n += 4) {
        float4 pa = *(float4*)&p_sm[(q0b + 0) * 260 + n];
        float4 pb2 = *(float4*)&p_sm[(q0b + 1) * 260 + n];
        float4 pc = *(float4*)&p_sm[(q0b + 2) * 260 + n];
        float4 pd = *(float4*)&p_sm[(q0b + 3) * 260 + n];
        float v0 = vs_sm[n * 33 + c2];
        float v1 = vs_sm[(n + 1) * 33 + c2];
        float v2 = vs_sm[(n + 2) * 33 + c2];
        float v3 = vs_sm[(n + 3) * 33 + c2];
        o0 += pa.x * v0 + pa.y * v1 + pa.z * v2 + pa.w * v3;
        o1 += pb2.x * v0 + pb2.y * v1 + pb2.z * v2 + pb2.w * v3;
        o2 += pc.x * v0 + pc.y * v1 + pc.z * v2 + pc.w * v3;
        o3 += pd.x * v0 + pd.y * v1 + pd.z * v2 + pd.w * v3;
    }
    __syncthreads();
    float* out_sm = q_sm;  // reuse (2112 >= 32*65)
    out_sm[c2 * 65 + q0b + 0] = o0;
    out_sm[c2 * 65 + q0b + 1] = o1;
    out_sm[c2 * 65 + q0b + 2] = o2;
    out_sm[c2 * 65 + q0b + 3] = o3;
    __syncthreads();

    float* aob = g_ao + ((size_t)(b * 128 + h * 32)) * HW_ + qbase;
    for (int i = tid; i < 2048; i += 512) {
        int c = i >> 6, qi = i & 63;
        aob[(size_t)c * HW_ + qi] = out_sm[c * 65 + qi];
    }
}

// ---------------- launch ----------------
extern "C" void kernel_launch(void* const* d_in, const int* in_sizes, int n_in,
                              void* d_out, int out_size)
{
    const float* x     = (const float*)d_in[0];
    const float* w_dw  = (const float*)d_in[1];
    const float* ln_w  = (const float*)d_in[2];
    const float* w_off = (const float*)d_in[3];
    const float* wq    = (const float*)d_in[4];
    const float* wk    = (const float*)d_in[5];
    const float* wv    = (const float*)d_in[6];
    const float* wo    = (const float*)d_in[7];
    const float* rpe   = (const float*)d_in[8];
    float* out = (float*)d_out;

    float *gq, *gao;
    cudaGetSymbolAddress((void**)&gq, g_q);
    cudaGetSymbolAddress((void**)&gao, g_ao);

    cudaFuncSetAttribute(gemm128_kernel, cudaFuncAttributeMaxDynamicSharedMemorySize, 131072);
    cudaFuncSetAttribute(gemm_kv_kernel, cudaFuncAttributeMaxDynamicSharedMemorySize, 131072);
    cudaFuncSetAttribute(attn_kernel, cudaFuncAttributeMaxDynamicSharedMemorySize,
                         ATTN_SMEM_FLOATS * 4);

    // q = wq * x
    gemm128_kernel<<<256, 256, 131072>>>(wq, x, gq, HW_, 32);
    // offset branch
    dwconv_kernel<<<1024, 256>>>(w_dw);
    offhead_kernel<<<16, 256>>>(ln_w, w_off);
    // deformable sampling
    sample_kernel<<<64, 256>>>(x);
    // k, v projections
    gemm_kv_kernel<<<32, 256, 131072>>>(wk, wv);
    // fused attention
    attn_kernel<<<2048, 512, ATTN_SMEM_FLOATS * 4>>>(rpe);
    // out = wo * attn_out
    gemm128_kernel<<<256, 256, 131072>>>(wo, gao, out, HW_, 32);
}

// round 3
// speedup vs baseline: 1.1841x; 1.1841x over previous
#include <cuda_runtime.h>
#include <math.h>

// ---------------- problem constants ----------------
#define B_   8
#define C_   128
#define HW_  4096
#define NKV_ 256
#define RPE_N 16129     // 127*127

typedef unsigned long long ull;

// ---------------- f32x2 packed-FMA helpers ----------------
__device__ __forceinline__ ull ffma2(ull a, ull b, ull c) {
    ull d;
    asm("fma.rn.f32x2 %0, %1, %2, %3;" : "=l"(d) : "l"(a), "l"(b), "l"(c));
    return d;
}
__device__ __forceinline__ ull pack2(float lo, float hi) {
    ull r;
    asm("mov.b64 %0, {%1, %2};" : "=l"(r) : "f"(lo), "f"(hi));
    return r;
}
__device__ __forceinline__ ull packs(float v) { return pack2(v, v); }
__device__ __forceinline__ float2 unpack2(ull v) {
    float x, y;
    asm("mov.b64 {%0, %1}, %2;" : "=f"(x), "=f"(y) : "l"(v));
    return make_float2(x, y);
}

// ---------------- device scratch (no runtime alloc) ----------------
__device__ float g_q  [B_ * C_ * HW_];
__device__ float g_ao [B_ * C_ * HW_];
__device__ float g_off[16 * 64 * NKV_];
__device__ float g_pos[16 * NKV_ * 2];
__device__ float g_dm [16 * NKV_];
__device__ float g_xs [B_ * C_ * NKV_];
__device__ float g_k  [B_ * C_ * NKV_];
__device__ float g_v  [B_ * C_ * NKV_];

// ---------------- 128x128 tile GEMM with f32x2 ----------------
__device__ __forceinline__ void gemm_tile(
    const float* __restrict__ A, const float* __restrict__ X,
    float* __restrict__ Y, int ld)
{
    extern __shared__ float sm[];
    float* a_sm = sm;           // [128][128]
    float* b_sm = sm + 16384;   // [128][128]
    int tid = threadIdx.x;

    for (int i = tid; i < 4096; i += 256)
        ((float4*)a_sm)[i] = ((const float4*)A)[i];
    for (int i = tid; i < 4096; i += 256) {
        int k = i >> 5, p4 = (i & 31) * 4;
        *(float4*)(b_sm + k * 128 + p4) = *(const float4*)(X + (size_t)k * ld + p4);
    }
    __syncthreads();

    int tr = tid >> 4, tc = tid & 15;
    int oc0 = tr * 8, p0 = tc * 8;
    ull acc[8][4];
#pragma unroll
    for (int i = 0; i < 8; i++)
#pragma unroll
        for (int j = 0; j < 4; j++) acc[i][j] = 0ull;

#pragma unroll 2
    for (int k = 0; k < 128; k += 2) {
        float2 a2[8];
#pragma unroll
        for (int i = 0; i < 8; i++)
            a2[i] = *(const float2*)&a_sm[(oc0 + i) * 128 + k];
        ulonglong2 b00 = *(const ulonglong2*)&b_sm[k * 128 + p0];
        ulonglong2 b01 = *(const ulonglong2*)&b_sm[k * 128 + p0 + 4];
        ulonglong2 b10 = *(const ulonglong2*)&b_sm[(k + 1) * 128 + p0];
        ulonglong2 b11 = *(const ulonglong2*)&b_sm[(k + 1) * 128 + p0 + 4];
        ull bb0[4] = {b00.x, b00.y, b01.x, b01.y};
        ull bb1[4] = {b10.x, b10.y, b11.x, b11.y};
#pragma unroll
        for (int i = 0; i < 8; i++) {
            ull aa0 = packs(a2[i].x);
            ull aa1 = packs(a2[i].y);
#pragma unroll
            for (int j = 0; j < 4; j++) acc[i][j] = ffma2(aa0, bb0[j], acc[i][j]);
#pragma unroll
            for (int j = 0; j < 4; j++) acc[i][j] = ffma2(aa1, bb1[j], acc[i][j]);
        }
    }
#pragma unroll
    for (int i = 0; i < 8; i++) {
        float* yr = Y + (size_t)(oc0 + i) * ld + p0;
        float2 r0 = unpack2(acc[i][0]), r1 = unpack2(acc[i][1]);
        float2 r2 = unpack2(acc[i][2]), r3 = unpack2(acc[i][3]);
        *(float4*)yr       = make_float4(r0.x, r0.y, r1.x, r1.y);
        *(float4*)(yr + 4) = make_float4(r2.x, r2.y, r3.x, r3.y);
    }
}

__global__ void __launch_bounds__(256) gemm128_kernel(
    const float* __restrict__ A, const float* __restrict__ X,
    float* __restrict__ Y, int ld, int ntiles)
{
    int b  = blockIdx.x / ntiles;
    int pb = (blockIdx.x % ntiles) * 128;
    gemm_tile(A, X + (size_t)b * 128 * ld + pb, Y + (size_t)b * 128 * ld + pb, ld);
}

__global__ void __launch_bounds__(256) gemm_kv_kernel(
    const float* __restrict__ wk, const float* __restrict__ wv)
{
    int sel = blockIdx.x >> 4;
    int r   = blockIdx.x & 15;
    int b   = r >> 1;
    int pb  = (r & 1) * 128;
    const float* A = sel ? wv : wk;
    float* Y = sel ? g_v : g_k;
    gemm_tile(A, g_xs + (size_t)b * 128 * NKV_ + pb, Y + (size_t)b * 128 * NKV_ + pb, NKV_);
}

// ---------------- depthwise 5x5 stride-4 pad-2 ----------------
__global__ void __launch_bounds__(256) dwconv_kernel(const float* __restrict__ w_dw)
{
    __shared__ float plane[4096];
    __shared__ float ws[25];
    int bid = blockIdx.x;
    int bg = bid >> 6, c = bid & 63;
    int b = bg >> 1, g = bg & 1;
    int tid = threadIdx.x;

    const float* src = g_q + ((size_t)(b * 128 + g * 64 + c)) * HW_;
    for (int i = tid; i < 1024; i += 256)
        ((float4*)plane)[i] = ((const float4*)src)[i];
    if (tid < 25) ws[tid] = w_dw[c * 25 + tid];
    __syncthreads();

    int i = tid >> 4, j = tid & 15;
    int y0 = 4 * i - 2, x0 = 4 * j - 2;
    float acc = 0.f;
#pragma unroll
    for (int u = 0; u < 5; u++) {
        int yy = y0 + u;
        if ((unsigned)yy < 64u) {
#pragma unroll
            for (int v = 0; v < 5; v++) {
                int xx = x0 + v;
                if ((unsigned)xx < 64u) acc += plane[yy * 64 + xx] * ws[u * 5 + v];
            }
        }
    }
    g_off[((size_t)(bg * 64 + c)) * NKV_ + tid] = acc;
}

// ---------------- LN(var-only) + GELU + 1x1 -> offsets/modulation ----------------
__global__ void __launch_bounds__(256) offhead_kernel(
    const float* __restrict__ ln_w, const float* __restrict__ w_off)
{
    int bg = blockIdx.x;
    int sp = threadIdx.x;
    const float* base = g_off + (size_t)bg * 64 * NKV_ + sp;
    float v[64];
    float s = 0.f, s2 = 0.f;
#pragma unroll
    for (int c = 0; c < 64; c++) {
        float t = base[c * NKV_];
        v[c] = t; s += t; s2 += t * t;
    }
    float mean = s * (1.f / 64.f);
    float var  = s2 * (1.f / 64.f) - mean * mean;
    float rstd = rsqrtf(var + 1e-5f);

    float o0 = 0.f, o1 = 0.f, o2 = 0.f;
#pragma unroll
    for (int c = 0; c < 64; c++) {
        float t = v[c] * rstd * __ldg(&ln_w[c]);
        float ge = 0.5f * t * (1.f + erff(t * 0.70710678118654752f));
        o0 += __ldg(&w_off[c]) * ge;
        o1 += __ldg(&w_off[64 + c]) * ge;
        o2 += __ldg(&w_off[128 + c]) * ge;
    }
    int i = sp >> 4, j = sp & 15;
    float ry = (float)(2 * i + 1) * (1.f / 16.f) - 1.f;
    float rx = (float)(2 * j + 1) * (1.f / 16.f) - 1.f;
    g_pos[bg * 512 + sp * 2]     = tanhf(o0) * (1.f / 16.f) + ry;
    g_pos[bg * 512 + sp * 2 + 1] = tanhf(o1) * (1.f / 16.f) + rx;
    g_dm [bg * 256 + sp]         = 1.f / (1.f + expf(-o2));
}

// ---------------- bilinear sample of x at deformed points ----------------
__global__ void __launch_bounds__(256) sample_kernel(const float* __restrict__ x)
{
    int blk = blockIdx.x;                // 256 = 16 bg x 16 nchunk
    int bg = blk >> 4;
    int n0 = (blk & 15) * 16;
    int b = bg >> 1, g = bg & 1;
    int c = threadIdx.x & 63;
    int ni = threadIdx.x >> 6;
    const float* plane = x + ((size_t)(b * 128 + g * 64 + c)) * HW_;
    for (int nn = ni; nn < 16; nn += 4) {
        int n = n0 + nn;
        float py_ = g_pos[bg * 512 + n * 2];
        float px_ = g_pos[bg * 512 + n * 2 + 1];
        float dmv = g_dm[bg * 256 + n];
        float gx = (px_ + 1.f) * 31.5f;
        float gy = (py_ + 1.f) * 31.5f;
        float x0f = floorf(gx), y0f = floorf(gy);
        float wx = gx - x0f, wy = gy - y0f;
        int ix0 = (int)x0f, iy0 = (int)y0f;
        float v00 = 0.f, v01 = 0.f, v10 = 0.f, v11 = 0.f;
        bool xin0 = (unsigned)ix0 < 64u, xin1 = (unsigned)(ix0 + 1) < 64u;
        bool yin0 = (unsigned)iy0 < 64u, yin1 = (unsigned)(iy0 + 1) < 64u;
        if (yin0) { int r = iy0 * 64;       if (xin0) v00 = plane[r + ix0]; if (xin1) v01 = plane[r + ix0 + 1]; }
        if (yin1) { int r = (iy0 + 1) * 64; if (xin0) v10 = plane[r + ix0]; if (xin1) v11 = plane[r + ix0 + 1]; }
        float top = v00 + (v01 - v00) * wx;
        float bot = v10 + (v11 - v10) * wx;
        float val = top + (bot - top) * wy;
        g_xs[((size_t)(b * 128 + g * 64 + c)) * NKV_ + n] = val * dmv;
    }
}

// ---------------- fused attention: QK + rpe-bias + softmax + PV ----------------
// grid = 32 heads x 32 tile-pairs; block = 512 thr; 208 KB smem, 1 block/SM
#define SM_RPE  0
#define SM_K    16132
#define SM_VS   (16132 + 8192)
#define SM_Q    (SM_VS + 8448)
#define SM_POS  (SM_Q + 2112)
#define SM_P    (SM_POS + 512)
#define ATTN_SMEM_FLOATS (SM_P + 64 * 260)

__global__ void __launch_bounds__(512) attn_kernel(const float* __restrict__ rpe)
{
    extern __shared__ float sm[];
    float* rpe_sm = sm + SM_RPE;
    float* k_sm   = sm + SM_K;
    float* vs_sm  = sm + SM_VS;
    float* q_sm   = sm + SM_Q;
    float* pos_sm = sm + SM_POS;
    float* p_sm   = sm + SM_P;

    int tid = threadIdx.x;
    int bh    = blockIdx.x >> 5;
    int group = blockIdx.x & 31;
    int b = bh >> 2, h = bh & 3, g = h >> 1;

    // ---- per-head loads (once) ----
    const float* rp = rpe + (size_t)h * RPE_N;
    for (int i = tid; i < RPE_N; i += 512) rpe_sm[i] = rp[i];

    const float* kb = g_k + ((size_t)(b * 128 + h * 32)) * NKV_;
    for (int i = tid; i < 2048; i += 512)
        ((float4*)k_sm)[i] = ((const float4*)kb)[i];

    const float* vb = g_v + ((size_t)(b * 128 + h * 32)) * NKV_;
    for (int i = tid; i < 8192; i += 512) {
        int c = i >> 8, n = i & 255;
        vs_sm[n * 33 + c] = vb[c * 256 + n];
    }
    pos_sm[tid] = g_pos[(size_t)(b * 2 + g) * 512 + tid];

    int w = tid >> 5, l = tid & 31;
    int q0 = w * 4;
    int nb = l * 8;

    for (int t = 0; t < 2; t++) {
        int tile = group * 2 + t;
        int qbase = tile * 64;
        __syncthreads();    // protects q_sm reuse from previous tile's out stage

        const float* qb = g_q + ((size_t)(b * 128 + h * 32)) * HW_ + qbase;
        for (int i = tid; i < 2048; i += 512) {
            int c = i >> 6, qi = i & 63;
            q_sm[qi * 33 + c] = qb[(size_t)c * HW_ + qi];
        }
        __syncthreads();

        // ---- phase A: QK (f32x2) + bias + softmax ----
        float py[8], px[8];
#pragma unroll
        for (int j = 0; j < 8; j++) {
            py[j] = pos_sm[(nb + j) * 2];
            px[j] = pos_sm[(nb + j) * 2 + 1];
        }
        ull acc[4][4];
#pragma unroll
        for (int i = 0; i < 4; i++)
#pragma unroll
            for (int j = 0; j < 4; j++) acc[i][j] = 0ull;

#pragma unroll 4
        for (int c = 0; c < 32; c++) {
            ulonglong2 k0 = *(const ulonglong2*)&k_sm[c * 256 + nb];
            ulonglong2 k1 = *(const ulonglong2*)&k_sm[c * 256 + nb + 4];
#pragma unroll
            for (int i = 0; i < 4; i++) {
                ull qq = packs(q_sm[(q0 + i) * 33 + c]);
                acc[i][0] = ffma2(qq, k0.x, acc[i][0]);
                acc[i][1] = ffma2(qq, k0.y, acc[i][1]);
                acc[i][2] = ffma2(qq, k1.x, acc[i][2]);
                acc[i][3] = ffma2(qq, k1.y, acc[i][3]);
            }
        }

        const float scale = 0.17677669529663687f;
#pragma unroll
        for (int i = 0; i < 4; i++) {
            int m = qbase + q0 + i;
            float qy = (float)(2 * (m >> 6) + 1) * (1.f / 64.f) - 1.f;
            float qx = (float)(2 * (m & 63) + 1) * (1.f / 64.f) - 1.f;
            float sv[8];
            {
                float2 u0 = unpack2(acc[i][0]), u1 = unpack2(acc[i][1]);
                float2 u2 = unpack2(acc[i][2]), u3 = unpack2(acc[i][3]);
                sv[0] = u0.x; sv[1] = u0.y; sv[2] = u1.x; sv[3] = u1.y;
                sv[4] = u2.x; sv[5] = u2.y; sv[6] = u3.x; sv[7] = u3.y;
            }
#pragma unroll
            for (int j = 0; j < 8; j++) {
                float gx = ((qx - px[j]) * 0.5f + 1.f) * 63.f;
                float gy = ((qy - py[j]) * 0.5f + 1.f) * 63.f;
                float x0f = floorf(gx), y0f = floorf(gy);
                float wx = gx - x0f, wy = gy - y0f;
                int ix0 = (int)x0f, iy0 = (int)y0f;
                float v00 = 0.f, v01 = 0.f, v10 = 0.f, v11 = 0.f;
                bool xin0 = (unsigned)ix0 < 127u, xin1 = (unsigned)(ix0 + 1) < 127u;
                bool yin0 = (unsigned)iy0 < 127u, yin1 = (unsigned)(iy0 + 1) < 127u;
                if (yin0) { int r = iy0 * 127;       if (xin0) v00 = rpe_sm[r + ix0]; if (xin1) v01 = rpe_sm[r + ix0 + 1]; }
                if (yin1) { int r = (iy0 + 1) * 127; if (xin0) v10 = rpe_sm[r + ix0]; if (xin1) v11 = rpe_sm[r + ix0 + 1]; }
                float top = v00 + (v01 - v00) * wx;
                float bot = v10 + (v11 - v10) * wx;
                sv[j] = sv[j] * scale + (top + (bot - top) * wy);
            }
            float mx = sv[0];
#pragma unroll
            for (int j = 1; j < 8; j++) mx = fmaxf(mx, sv[j]);
#pragma unroll
            for (int o = 16; o; o >>= 1) mx = fmaxf(mx, __shfl_xor_sync(0xffffffffu, mx, o));
            float sum = 0.f;
#pragma unroll
            for (int j = 0; j < 8; j++) { float e = __expf(sv[j] - mx); sv[j] = e; sum += e; }
#pragma unroll
            for (int o = 16; o; o >>= 1) sum += __shfl_xor_sync(0xffffffffu, sum, o);
            float inv = 1.f / sum;
            *(float4*)&p_sm[(q0 + i) * 260 + nb]     = make_float4(sv[0] * inv, sv[1] * inv, sv[2] * inv, sv[3] * inv);
            *(float4*)&p_sm[(q0 + i) * 260 + nb + 4] = make_float4(sv[4] * inv, sv[5] * inv, sv[6] * inv, sv[7] * inv);
        }
        __syncthreads();

        // ---- phase B: PV (f32x2, packed along n) ----
        int c2 = tid & 31, qg = tid >> 5;
        int q0b = qg * 4;
        ull o[4] = {0ull, 0ull, 0ull, 0ull};
#pragma unroll 4
        for (int n = 0; n < 256; n += 4) {
            float v0 = vs_sm[n * 33 + c2];
            float v1 = vs_sm[(n + 1) * 33 + c2];
            float v2 = vs_sm[(n + 2) * 33 + c2];
            float v3 = vs_sm[(n + 3) * 33 + c2];
            ull vp0 = pack2(v0, v1);
            ull vp1 = pack2(v2, v3);
#pragma unroll
            for (int i = 0; i < 4; i++) {
                ulonglong2 pp = *(const ulonglong2*)&p_sm[(q0b + i) * 260 + n];
                o[i] = ffma2(pp.x, vp0, o[i]);
                o[i] = ffma2(pp.y, vp1, o[i]);
            }
        }
        __syncthreads();
        float* out_sm = q_sm;  // reuse
        {
            float2 f0 = unpack2(o[0]), f1 = unpack2(o[1]);
            float2 f2 = unpack2(o[2]), f3 = unpack2(o[3]);
            out_sm[c2 * 65 + q0b + 0] = f0.x + f0.y;
            out_sm[c2 * 65 + q0b + 1] = f1.x + f1.y;
            out_sm[c2 * 65 + q0b + 2] = f2.x + f2.y;
            out_sm[c2 * 65 + q0b + 3] = f3.x + f3.y;
        }
        __syncthreads();

        float* aob = g_ao + ((size_t)(b * 128 + h * 32)) * HW_ + qbase;
        for (int i = tid; i < 2048; i += 512) {
            int c = i >> 6, qi = i & 63;
            aob[(size_t)c * HW_ + qi] = out_sm[c * 65 + qi];
        }
    }
}

// ---------------- launch ----------------
extern "C" void kernel_launch(void* const* d_in, const int* in_sizes, int n_in,
                              void* d_out, int out_size)
{
    const float* x     = (const float*)d_in[0];
    const float* w_dw  = (const float*)d_in[1];
    const float* ln_w  = (const float*)d_in[2];
    const float* w_off = (const float*)d_in[3];
    const float* wq    = (const float*)d_in[4];
    const float* wk    = (const float*)d_in[5];
    const float* wv    = (const float*)d_in[6];
    const float* wo    = (const float*)d_in[7];
    const float* rpe   = (const float*)d_in[8];
    float* out = (float*)d_out;

    float *gq, *gao;
    cudaGetSymbolAddress((void**)&gq, g_q);
    cudaGetSymbolAddress((void**)&gao, g_ao);

    cudaFuncSetAttribute(gemm128_kernel, cudaFuncAttributeMaxDynamicSharedMemorySize, 131072);
    cudaFuncSetAttribute(gemm_kv_kernel, cudaFuncAttributeMaxDynamicSharedMemorySize, 131072);
    cudaFuncSetAttribute(attn_kernel, cudaFuncAttributeMaxDynamicSharedMemorySize,
                         ATTN_SMEM_FLOATS * 4);

    gemm128_kernel<<<256, 256, 131072>>>(wq, x, gq, HW_, 32);
    dwconv_kernel<<<1024, 256>>>(w_dw);
    offhead_kernel<<<16, 256>>>(ln_w, w_off);
    sample_kernel<<<256, 256>>>(x);
    gemm_kv_kernel<<<32, 256, 131072>>>(wk, wv);
    attn_kernel<<<1024, 512, ATTN_SMEM_FLOATS * 4>>>(rpe);
    gemm128_kernel<<<256, 256, 131072>>>(wo, gao, out, HW_, 32);
}